// round 8
// baseline (speedup 1.0000x reference)
#include <cuda_runtime.h>
#include <cuda_fp16.h>
#include <cstdint>
#include <cstddef>

// ============================================================
// out = L1rownorm(A[8192,8192]) @ X[8192,512] @ W[512,256] + bias
//   Xh = fp16(X), Wth = fp16(W^T)
//   Yt[256,8192](fp16) = Wth @ Xh^T              (fp16 HMMA)
//   GEMM2: 296 persistent-ish CTAs, static balanced chunk ranges,
//          raw fp32 partials + partial rowsums -> reduce kernel.
// ============================================================

#define N_ROWS 8192
#define F_IN   512
#define F_OUT  256

// ---- GEMM1 (fp16, cp.async both operands) ----
#define G1_ST  (128 * 40 * 2)
#define G1_STAGE (2 * G1_ST)
#define G1_SMEM (3 * G1_STAGE)       // 61440

// ---- GEMM2: tile 128x64, 296 CTAs, balanced ----
#define T2_M 128
#define T2_N 64
#define CK 32
#define PAH 40                        // halves per smem row (80 B)
#define A_ST  (T2_M * PAH * 2)        // 10240
#define B_ST  (T2_N * PAH * 2)        // 5120
#define B_OFF (2 * A_ST)              // 2 A stages
#define T2_SMEM (B_OFF + 6 * B_ST)    // 51200
#define NCTA2 296
// total work: 256 tiles * 256 chunks, tile-major global index

__device__ __align__(1024) __half g_Xh[(size_t)N_ROWS * F_IN];
__device__ __align__(1024) __half g_Wth[(size_t)F_OUT * F_IN];
__device__ __align__(1024) __half g_Yt[(size_t)F_OUT * N_ROWS];
__device__ __align__(1024) float  g_Part[(size_t)NCTA2 * 2 * T2_M * T2_N]; // 19.4 MB
__device__ __align__(1024) float  g_RSp[(size_t)NCTA2 * 2 * T2_M];

// ---------------- device helpers ----------------
__device__ __forceinline__ uint32_t pack_h2(float lo, float hi) {
    uint32_t u;
    asm("cvt.rn.f16x2.f32 %0, %1, %2;" : "=r"(u) : "f"(hi), "f"(lo));
    return u;
}
__device__ __forceinline__ void mma_f16_k16(float* c, const uint32_t* a, const uint32_t* b) {
    asm volatile(
        "mma.sync.aligned.m16n8k16.row.col.f32.f16.f16.f32 "
        "{%0,%1,%2,%3}, {%4,%5,%6,%7}, {%8,%9}, {%0,%1,%2,%3};"
        : "+f"(c[0]), "+f"(c[1]), "+f"(c[2]), "+f"(c[3])
        : "r"(a[0]), "r"(a[1]), "r"(a[2]), "r"(a[3]), "r"(b[0]), "r"(b[1]));
}
__device__ __forceinline__ void cpa16(uint32_t s, const void* g) {
    asm volatile("cp.async.cg.shared.global [%0], [%1], 16;" :: "r"(s), "l"(g));
}
__device__ __forceinline__ void ldsm4(uint32_t& r0, uint32_t& r1, uint32_t& r2, uint32_t& r3,
                                      uint32_t addr) {
    asm volatile("ldmatrix.sync.aligned.m8n8.x4.shared.b16 {%0,%1,%2,%3}, [%4];"
                 : "=r"(r0), "=r"(r1), "=r"(r2), "=r"(r3) : "r"(addr));
}
__device__ __forceinline__ uint32_t smem_u32(const void* p) {
    uint32_t a;
    asm("{ .reg .u64 t; cvta.to.shared.u64 t, %1; cvt.u32.u64 %0, t; }" : "=r"(a) : "l"(p));
    return a;
}
// Start of CTA c's global chunk range: floor(c * 8192 / 37)   (= c*65536/296)
__device__ __forceinline__ int rstart(int c) {
    return (int)(((long long)c << 13) / 37);
}

// ---------------- prep kernels ----------------
__global__ void __launch_bounds__(256, 1) prep_xh(const float* __restrict__ x,
                                                  __half* __restrict__ xh) {
    int i = blockIdx.x * 256 + threadIdx.x;
    float4 v = reinterpret_cast<const float4*>(x)[i];
    uint2 o;
    o.x = pack_h2(v.x, v.y);
    o.y = pack_h2(v.z, v.w);
    reinterpret_cast<uint2*>(xh)[i] = o;
}
__global__ void __launch_bounds__(256, 1) prep_wh(const float* __restrict__ w,
                                                  __half* __restrict__ wth) {
    int t = blockIdx.x * 256 + threadIdx.x;
    int fi = t & 511, fo = t >> 9;
    wth[t] = __float2half_rn(w[fi * F_OUT + fo]);
}

// ---------------- GEMM1 (fp16): Yt[256,8192] = Wth @ Xh^T ----------------
__global__ void __launch_bounds__(256, 1) gemm1_f16(
    const __half* __restrict__ P, const __half* __restrict__ Q,
    __half* __restrict__ out)
{
    extern __shared__ char smem[];
    const uint32_t sbase = smem_u32(smem);

    const int tid  = threadIdx.x;
    const int lane = tid & 31;
    const int wid  = tid >> 5;
    const int gid  = lane >> 2;
    const int tig  = lane & 3;
    const int wm   = wid >> 1;
    const int wn   = wid & 1;
    const int lrow = lane & 15;
    const int lhi  = (lane >> 4) & 1;

    const int mtile = blockIdx.x >> 6;
    const int ntile = blockIdx.x & 63;
    const int m0 = mtile * 128;
    const int n0 = ntile * 128;
    const int kchunks = F_IN / CK;

    const int rw = tid >> 2;
    const int sg = tid & 3;
    const __half* gA = P + (size_t)(m0 + rw) * F_IN + sg * 8;
    const __half* gB = Q + (size_t)(n0 + rw) * F_IN + sg * 8;

    auto issue = [&](int kc, int s) {
        uint32_t sA = sbase + s * G1_STAGE + rw * 80 + sg * 16;
        uint32_t sB = sA + G1_ST;
        cpa16(sA,           gA + kc * CK);
        cpa16(sA + 64 * 80, gA + kc * CK + (size_t)64 * F_IN);
        cpa16(sB,           gB + kc * CK);
        cpa16(sB + 64 * 80, gB + kc * CK + (size_t)64 * F_IN);
        asm volatile("cp.async.commit_group;" ::: "memory");
    };

    float acc[2][8][4];
    #pragma unroll
    for (int mi = 0; mi < 2; mi++)
        #pragma unroll
        for (int ni = 0; ni < 8; ni++)
            #pragma unroll
            for (int i = 0; i < 4; i++) acc[mi][ni][i] = 0.f;

    issue(0, 0);
    issue(1, 1);

    int s_c = 0, s_p = 2;
    for (int kc = 0; kc < kchunks; kc++) {
        asm volatile("cp.async.wait_group %0;" :: "n"(1) : "memory");
        __syncthreads();
        const uint32_t aBase = sbase + s_c * G1_STAGE;
        const uint32_t bBase = aBase + G1_ST;

        #pragma unroll
        for (int ks = 0; ks < 2; ks++) {
            uint32_t af[2][4], bf[8][2];
            #pragma unroll
            for (int mi = 0; mi < 2; mi++) {
                uint32_t ad = aBase + ((wm * 32 + mi * 16 + lrow) * PAH + ks * 16 + lhi * 8) * 2;
                ldsm4(af[mi][0], af[mi][1], af[mi][2], af[mi][3], ad);
            }
            #pragma unroll
            for (int np = 0; np < 4; np++) {
                uint32_t bd = bBase + ((wn * 64 + np * 16 + lrow) * PAH + ks * 16 + lhi * 8) * 2;
                uint32_t r0, r1, r2, r3;
                ldsm4(r0, r1, r2, r3, bd);
                bf[np * 2 + 0][0] = r0; bf[np * 2 + 0][1] = r2;
                bf[np * 2 + 1][0] = r1; bf[np * 2 + 1][1] = r3;
            }
            #pragma unroll
            for (int mi = 0; mi < 2; mi++)
                #pragma unroll
                for (int ni = 0; ni < 8; ni++)
                    mma_f16_k16(acc[mi][ni], af[mi], bf[ni]);
        }

        if (kc + 2 < kchunks) issue(kc + 2, s_p);
        else asm volatile("cp.async.commit_group;" ::: "memory");
        if (++s_c == 3) s_c = 0;
        if (++s_p == 3) s_p = 0;
    }

    #pragma unroll
    for (int mi = 0; mi < 2; mi++) {
        const int r0 = m0 + wm * 32 + mi * 16 + gid;
        #pragma unroll
        for (int ni = 0; ni < 8; ni++) {
            const int cg = n0 + wn * 64 + ni * 8 + tig * 2;
            *(uint32_t*)(out + (size_t)r0 * N_ROWS + cg) =
                pack_h2(acc[mi][ni][0], acc[mi][ni][1]);
            *(uint32_t*)(out + (size_t)(r0 + 8) * N_ROWS + cg) =
                pack_h2(acc[mi][ni][2], acc[mi][ni][3]);
        }
    }
}

// ---------------- GEMM2: balanced partials ----------------
__global__ void __launch_bounds__(256, 2) gemm2_f16(
    const float* __restrict__ A, const __half* __restrict__ Yt,
    float* __restrict__ part, float* __restrict__ rsp)
{
    extern __shared__ char smem[];
    const uint32_t sbase = smem_u32(smem);

    const int tid  = threadIdx.x;
    const int lane = tid & 31;
    const int wid  = tid >> 5;
    const int gid  = lane >> 2;
    const int tig  = lane & 3;
    const int wm   = wid >> 1;            // 0..3 (M strips of 32)
    const int wn   = wid & 1;             // 0..1 (N strips of 32)
    const int lrow = lane & 15;
    const int lhi  = (lane >> 4) & 1;

    const int ra = tid >> 3;              // 0..31 (A row mod 32)
    const int sa = tid & 7;               // 0..7  (A 16B segment)
    const int rb = tid >> 2;              // 0..63 (B row)
    const int sb = tid & 3;               // 0..3  (B 16B segment)

    const int cta = blockIdx.x;
    const int g0 = rstart(cta);
    const int g1 = rstart(cta + 1);

    #pragma unroll 1
    for (int seg = 0; seg < 2; seg++) {
        const int tile = (g0 >> 8) + seg;
        const int tst  = tile << 8;
        const int ks = (g0 > tst) ? (g0 - tst) : 0;
        const int ke = min(g1 - tst, 256);
        if (ke <= ks) break;

        const int m0 = (tile >> 2) * T2_M;
        const int n0 = (tile & 3) * T2_N;
        const float*  gA = A  + (size_t)(m0 + ra) * N_ROWS + sa * 4;
        const __half* gB = Yt + (size_t)(n0 + rb) * N_ROWS + sb * 8;

        float acc[2][4][4];
        #pragma unroll
        for (int mi = 0; mi < 2; mi++)
            #pragma unroll
            for (int ni = 0; ni < 4; ni++)
                #pragma unroll
                for (int i = 0; i < 4; i++) acc[mi][ni][i] = 0.f;
        float rsum[4] = {0.f, 0.f, 0.f, 0.f};

        __syncthreads();   // all prior-segment smem reads complete before reuse

        auto issueB = [&](int kc, int s6) {
            if (kc < ke)
                cpa16(sbase + B_OFF + s6 * B_ST + rb * (PAH * 2) + sb * 16,
                      gB + (size_t)kc * CK);
            asm volatile("cp.async.commit_group;" ::: "memory");
        };
        auto ldA = [&](int kc, float4* v) {
            #pragma unroll
            for (int i = 0; i < 4; i++)
                v[i] = *(const float4*)(gA + (size_t)i * 32 * N_ROWS + (size_t)kc * CK);
        };

        float4 vA[4];
        ldA(ks, vA);
        issueB(ks + 0, 0);
        issueB(ks + 1, 1);
        issueB(ks + 2, 2);
        issueB(ks + 3, 3);

        int s6c = 0, s6p = 4, p2 = 0;
        for (int kc = ks; kc < ke; kc++) {
            asm volatile("cp.async.wait_group %0;" :: "n"(3) : "memory");

            // producer: STS fp16 A + rowsum, prefetch next A chunk
            const uint32_t aw = sbase + p2 * A_ST + ra * (PAH * 2) + sa * 8;
            #pragma unroll
            for (int i = 0; i < 4; i++) {
                uint32_t h01 = pack_h2(vA[i].x, vA[i].y);
                uint32_t h23 = pack_h2(vA[i].z, vA[i].w);
                asm volatile("st.shared.v2.b32 [%0], {%1,%2};"
                             :: "r"(aw + i * 32 * (PAH * 2)), "r"(h01), "r"(h23));
                rsum[i] += (vA[i].x + vA[i].y) + (vA[i].z + vA[i].w);
            }
            const int kn = (kc + 1 < ke) ? kc + 1 : kc;
            ldA(kn, vA);

            __syncthreads();

            issueB(kc + 4, s6p);

            // consumer: ldmatrix + MMA
            const uint32_t aBase = sbase + p2 * A_ST;
            const uint32_t bBase = sbase + B_OFF + s6c * B_ST;
            #pragma unroll
            for (int kh = 0; kh < 2; kh++) {
                uint32_t af[2][4], bf[4][2];
                #pragma unroll
                for (int mi = 0; mi < 2; mi++) {
                    uint32_t ad = aBase + ((wm * 32 + mi * 16 + lrow) * PAH + kh * 16 + lhi * 8) * 2;
                    ldsm4(af[mi][0], af[mi][1], af[mi][2], af[mi][3], ad);
                }
                #pragma unroll
                for (int np = 0; np < 2; np++) {
                    uint32_t bd = bBase + ((wn * 32 + np * 16 + lrow) * PAH + kh * 16 + lhi * 8) * 2;
                    uint32_t r0, r1, r2, r3;
                    ldsm4(r0, r1, r2, r3, bd);
                    bf[np * 2 + 0][0] = r0; bf[np * 2 + 0][1] = r2;
                    bf[np * 2 + 1][0] = r1; bf[np * 2 + 1][1] = r3;
                }
                #pragma unroll
                for (int mi = 0; mi < 2; mi++)
                    #pragma unroll
                    for (int ni = 0; ni < 4; ni++)
                        mma_f16_k16(acc[mi][ni], af[mi], bf[ni]);
            }

            s6c = (s6c == 5) ? 0 : s6c + 1;
            s6p = (s6p == 5) ? 0 : s6p + 1;
            p2 ^= 1;
        }

        // ---- segment epilogue ----
        const size_t slot = (size_t)(cta * 2 + seg);

        // partial rowsum (only tiles with ntile==0 contribute)
        #pragma unroll
        for (int i = 0; i < 4; i++) {
            rsum[i] += __shfl_down_sync(0xffffffffu, rsum[i], 4, 8);
            rsum[i] += __shfl_down_sync(0xffffffffu, rsum[i], 2, 8);
            rsum[i] += __shfl_down_sync(0xffffffffu, rsum[i], 1, 8);
        }
        if ((tile & 3) == 0 && sa == 0) {
            #pragma unroll
            for (int i = 0; i < 4; i++)
                rsp[slot * T2_M + i * 32 + ra] = rsum[i];
        }

        // partial acc tile [128 x 64]
        float* pout = part + slot * (T2_M * T2_N);
        #pragma unroll
        for (int mi = 0; mi < 2; mi++) {
            const int r0 = wm * 32 + mi * 16 + gid;
            #pragma unroll
            for (int ni = 0; ni < 4; ni++) {
                const int cg = wn * 32 + ni * 8 + tig * 2;
                float2 v0, v1;
                v0.x = acc[mi][ni][0]; v0.y = acc[mi][ni][1];
                v1.x = acc[mi][ni][2]; v1.y = acc[mi][ni][3];
                *(float2*)(pout + (size_t)r0 * T2_N + cg) = v0;
                *(float2*)(pout + (size_t)(r0 + 8) * T2_N + cg) = v1;
            }
        }
    }
}

// ---------------- reduce: gather partials, normalize, bias ----------------
__global__ void __launch_bounds__(256, 4) reduce_out(
    const float* __restrict__ part, const float* __restrict__ rsp,
    const float* __restrict__ bias, float* __restrict__ out)
{
    const int idx = blockIdx.x * 256 + threadIdx.x;   // over float4: 8192*64
    const int row = idx >> 6;
    const int col = (idx & 63) << 2;

    // gather rowsum over covering segments of tile (mtile, n=0)
    float rs = 0.f;
    {
        const int tm = (row >> 7) << 2;
        const int gLo = tm << 8, gHi = gLo + 256;
        int c = (int)(((long long)gLo * 37) >> 13);
        while (rstart(c + 1) <= gLo) c++;
        while (rstart(c) > gLo) c--;
        for (;; c++) {
            int sc = rstart(c);
            if (sc >= gHi) break;
            int sg = ((sc >> 8) == tm) ? 0 : 1;
            rs += rsp[(size_t)(c * 2 + sg) * T2_M + (row & 127)];
        }
    }

    // gather partial sums over covering segments of this tile
    float4 s = make_float4(0.f, 0.f, 0.f, 0.f);
    {
        const int t = ((row >> 7) << 2) + (col >> 6);
        const int gLo = t << 8, gHi = gLo + 256;
        int c = (int)(((long long)gLo * 37) >> 13);
        while (rstart(c + 1) <= gLo) c++;
        while (rstart(c) > gLo) c--;
        for (;; c++) {
            int sc = rstart(c);
            if (sc >= gHi) break;
            int sg = ((sc >> 8) == t) ? 0 : 1;
            const float4 p = *(const float4*)(part +
                (size_t)(c * 2 + sg) * (T2_M * T2_N) + ((row & 127) << 6) + (col & 63));
            s.x += p.x; s.y += p.y; s.z += p.z; s.w += p.w;
        }
    }

    const float inv = 1.f / fmaxf(rs, 1e-12f);
    const float4 bv = *(const float4*)(bias + col);
    float4 o;
    o.x = s.x * inv + bv.x;
    o.y = s.y * inv + bv.y;
    o.z = s.z * inv + bv.z;
    o.w = s.w * inv + bv.w;
    *(float4*)(out + (size_t)row * F_OUT + col) = o;
}

// ---------------- host ----------------
extern "C" void kernel_launch(void* const* d_in, const int* in_sizes, int n_in,
                              void* d_out, int out_size) {
    const float *A = nullptr, *X = nullptr, *W = nullptr, *Bi = nullptr;
    for (int i = 0; i < n_in; i++) {
        long s = in_sizes[i];
        if (s == (long)N_ROWS * N_ROWS)      A  = (const float*)d_in[i];
        else if (s == (long)N_ROWS * F_IN)   X  = (const float*)d_in[i];
        else if (s == (long)F_IN * F_OUT)    W  = (const float*)d_in[i];
        else if (s == (long)F_OUT)           Bi = (const float*)d_in[i];
    }

    void *xh = nullptr, *wth = nullptr, *yt = nullptr, *pt = nullptr, *rs = nullptr;
    cudaGetSymbolAddress(&xh, g_Xh);
    cudaGetSymbolAddress(&wth, g_Wth);
    cudaGetSymbolAddress(&yt, g_Yt);
    cudaGetSymbolAddress(&pt, g_Part);
    cudaGetSymbolAddress(&rs, g_RSp);

    cudaFuncSetAttribute(gemm1_f16, cudaFuncAttributeMaxDynamicSharedMemorySize, G1_SMEM);
    cudaFuncSetAttribute(gemm2_f16, cudaFuncAttributeMaxDynamicSharedMemorySize, T2_SMEM);

    prep_xh<<<(N_ROWS * F_IN / 4) / 256, 256>>>(X, (__half*)xh);
    prep_wh<<<(F_IN * F_OUT) / 256, 256>>>(W, (__half*)wth);

    // GEMM1: Yt[256,8192] = Wth @ Xh^T
    gemm1_f16<<<2 * 64, 256, G1_SMEM>>>((const __half*)wth, (const __half*)xh, (__half*)yt);

    // GEMM2: 296 balanced CTAs -> partials
    gemm2_f16<<<NCTA2, 256, T2_SMEM>>>(A, (const __half*)yt, (float*)pt, (float*)rs);

    // reduce: out = sum(partials)/rowsum + bias
    reduce_out<<<(N_ROWS * F_OUT / 4) / 256, 256>>>((const float*)pt, (const float*)rs,
                                                    Bi, (float*)d_out);
}

// round 9
// speedup vs baseline: 1.1106x; 1.1106x over previous
#include <cuda_runtime.h>
#include <cuda_fp16.h>
#include <cstdint>
#include <cstddef>

// ============================================================
// out = L1rownorm(A[8192,8192]) @ X[8192,512] @ W[512,256] + bias
//   Xh = fp16(X), Wth = fp16(W^T)
//   Yt[256,8192](fp16) = Wth @ Xh^T              (fp16 HMMA)
//   GEMM2: 296 CTAs. Tiles 128x64 (bid<256, k-phase aligned);
//     heavy tiles do k<KH, 40 helpers (bid>=256) do the k-tails,
//     placed on the light SMs via smid = LUT[bid % 148].
//   reduce: out = (P1 + P2)/(RS1 + RS2) + bias
// ============================================================

#define N_ROWS 8192
#define F_IN   512
#define F_OUT  256

// ---- GEMM1 (fp16, cp.async both operands) ----
#define G1_ST  (128 * 40 * 2)
#define G1_STAGE (2 * G1_ST)
#define G1_SMEM (3 * G1_STAGE)       // 61440

// ---- GEMM2: tile 128x64 ----
#define T2_M 128
#define T2_N 64
#define CK 32
#define PAH 40                        // halves per smem row (80 B)
#define A_ST  (T2_M * PAH * 2)        // 10240
#define B_ST  (T2_N * PAH * 2)        // 5120
#define B_OFF (2 * A_ST)
#define T2_SMEM (B_OFF + 6 * B_ST)    // 51200 -> 2 CTAs/SM

#define KH 221                        // heavy-tile main k-chunks
#define LT0 108                       // light tiles [108,148)
#define LT1 148

__device__ __align__(1024) __half g_Xh[(size_t)N_ROWS * F_IN];
__device__ __align__(1024) __half g_Wth[(size_t)F_OUT * F_IN];
__device__ __align__(1024) __half g_Yt[(size_t)F_OUT * N_ROWS];
__device__ __align__(1024) float  g_P1[(size_t)N_ROWS * F_OUT];   // main partials
__device__ __align__(1024) float  g_P2[(size_t)N_ROWS * F_OUT];   // tail partials
__device__ __align__(1024) float  g_RS1[N_ROWS];
__device__ __align__(1024) float  g_RS2[N_ROWS];

// ---------------- device helpers ----------------
__device__ __forceinline__ uint32_t pack_h2(float lo, float hi) {
    uint32_t u;
    asm("cvt.rn.f16x2.f32 %0, %1, %2;" : "=r"(u) : "f"(hi), "f"(lo));
    return u;
}
__device__ __forceinline__ void mma_f16_k16(float* c, const uint32_t* a, const uint32_t* b) {
    asm volatile(
        "mma.sync.aligned.m16n8k16.row.col.f32.f16.f16.f32 "
        "{%0,%1,%2,%3}, {%4,%5,%6,%7}, {%8,%9}, {%0,%1,%2,%3};"
        : "+f"(c[0]), "+f"(c[1]), "+f"(c[2]), "+f"(c[3])
        : "r"(a[0]), "r"(a[1]), "r"(a[2]), "r"(a[3]), "r"(b[0]), "r"(b[1]));
}
__device__ __forceinline__ void cpa16(uint32_t s, const void* g) {
    asm volatile("cp.async.cg.shared.global [%0], [%1], 16;" :: "r"(s), "l"(g));
}
__device__ __forceinline__ void ldsm4(uint32_t& r0, uint32_t& r1, uint32_t& r2, uint32_t& r3,
                                      uint32_t addr) {
    asm volatile("ldmatrix.sync.aligned.m8n8.x4.shared.b16 {%0,%1,%2,%3}, [%4];"
                 : "=r"(r0), "=r"(r1), "=r"(r2), "=r"(r3) : "r"(addr));
}
__device__ __forceinline__ uint32_t smem_u32(const void* p) {
    uint32_t a;
    asm("{ .reg .u64 t; cvta.to.shared.u64 t, %1; cvt.u32.u64 %0, t; }" : "=r"(a) : "l"(p));
    return a;
}

// ---------------- prep kernels ----------------
__global__ void __launch_bounds__(256, 1) prep_xh(const float* __restrict__ x,
                                                  __half* __restrict__ xh) {
    int i = blockIdx.x * 256 + threadIdx.x;
    float4 v = reinterpret_cast<const float4*>(x)[i];
    uint2 o;
    o.x = pack_h2(v.x, v.y);
    o.y = pack_h2(v.z, v.w);
    reinterpret_cast<uint2*>(xh)[i] = o;
}
// coalesced transpose W[512,256] -> Wth[256,512] (fp16)
__global__ void __launch_bounds__(256, 1) prep_wt(const float* __restrict__ w,
                                                  __half* __restrict__ wth) {
    __shared__ float t[32][33];
    const int tx = threadIdx.x & 31;
    const int ty = threadIdx.x >> 5;          // 0..7
    const int fo0 = blockIdx.x * 32;          // 8 blocks
    const int fi0 = blockIdx.y * 32;          // 16 blocks
    #pragma unroll
    for (int r = 0; r < 32; r += 8)
        t[ty + r][tx] = w[(size_t)(fi0 + ty + r) * F_OUT + fo0 + tx];
    __syncthreads();
    #pragma unroll
    for (int r = 0; r < 32; r += 8)
        wth[(size_t)(fo0 + ty + r) * F_IN + fi0 + tx] = __float2half_rn(t[tx][ty + r]);
}

// ---------------- GEMM1 (fp16): Yt[256,8192] = Wth @ Xh^T ----------------
__global__ void __launch_bounds__(256, 1) gemm1_f16(
    const __half* __restrict__ P, const __half* __restrict__ Q,
    __half* __restrict__ out)
{
    extern __shared__ char smem[];
    const uint32_t sbase = smem_u32(smem);

    const int tid  = threadIdx.x;
    const int lane = tid & 31;
    const int wid  = tid >> 5;
    const int gid  = lane >> 2;
    const int tig  = lane & 3;
    const int wm   = wid >> 1;
    const int wn   = wid & 1;
    const int lrow = lane & 15;
    const int lhi  = (lane >> 4) & 1;

    const int mtile = blockIdx.x >> 6;
    const int ntile = blockIdx.x & 63;
    const int m0 = mtile * 128;
    const int n0 = ntile * 128;
    const int kchunks = F_IN / CK;

    const int rw = tid >> 2;
    const int sg = tid & 3;
    const __half* gA = P + (size_t)(m0 + rw) * F_IN + sg * 8;
    const __half* gB = Q + (size_t)(n0 + rw) * F_IN + sg * 8;

    auto issue = [&](int kc, int s) {
        uint32_t sA = sbase + s * G1_STAGE + rw * 80 + sg * 16;
        uint32_t sB = sA + G1_ST;
        cpa16(sA,           gA + kc * CK);
        cpa16(sA + 64 * 80, gA + kc * CK + (size_t)64 * F_IN);
        cpa16(sB,           gB + kc * CK);
        cpa16(sB + 64 * 80, gB + kc * CK + (size_t)64 * F_IN);
        asm volatile("cp.async.commit_group;" ::: "memory");
    };

    float acc[2][8][4];
    #pragma unroll
    for (int mi = 0; mi < 2; mi++)
        #pragma unroll
        for (int ni = 0; ni < 8; ni++)
            #pragma unroll
            for (int i = 0; i < 4; i++) acc[mi][ni][i] = 0.f;

    issue(0, 0);
    issue(1, 1);

    int s_c = 0, s_p = 2;
    for (int kc = 0; kc < kchunks; kc++) {
        asm volatile("cp.async.wait_group %0;" :: "n"(1) : "memory");
        __syncthreads();
        const uint32_t aBase = sbase + s_c * G1_STAGE;
        const uint32_t bBase = aBase + G1_ST;

        #pragma unroll
        for (int ks = 0; ks < 2; ks++) {
            uint32_t af[2][4], bf[8][2];
            #pragma unroll
            for (int mi = 0; mi < 2; mi++) {
                uint32_t ad = aBase + ((wm * 32 + mi * 16 + lrow) * PAH + ks * 16 + lhi * 8) * 2;
                ldsm4(af[mi][0], af[mi][1], af[mi][2], af[mi][3], ad);
            }
            #pragma unroll
            for (int np = 0; np < 4; np++) {
                uint32_t bd = bBase + ((wn * 64 + np * 16 + lrow) * PAH + ks * 16 + lhi * 8) * 2;
                uint32_t r0, r1, r2, r3;
                ldsm4(r0, r1, r2, r3, bd);
                bf[np * 2 + 0][0] = r0; bf[np * 2 + 0][1] = r2;
                bf[np * 2 + 1][0] = r1; bf[np * 2 + 1][1] = r3;
            }
            #pragma unroll
            for (int mi = 0; mi < 2; mi++)
                #pragma unroll
                for (int ni = 0; ni < 8; ni++)
                    mma_f16_k16(acc[mi][ni], af[mi], bf[ni]);
        }

        if (kc + 2 < kchunks) issue(kc + 2, s_p);
        else asm volatile("cp.async.commit_group;" ::: "memory");
        if (++s_c == 3) s_c = 0;
        if (++s_p == 3) s_p = 0;
    }

    #pragma unroll
    for (int mi = 0; mi < 2; mi++) {
        const int r0 = m0 + wm * 32 + mi * 16 + gid;
        #pragma unroll
        for (int ni = 0; ni < 8; ni++) {
            const int cg = n0 + wn * 64 + ni * 8 + tig * 2;
            *(uint32_t*)(out + (size_t)r0 * N_ROWS + cg) =
                pack_h2(acc[mi][ni][0], acc[mi][ni][1]);
            *(uint32_t*)(out + (size_t)(r0 + 8) * N_ROWS + cg) =
                pack_h2(acc[mi][ni][2], acc[mi][ni][3]);
        }
    }
}

// ---------------- GEMM2: tiles + paired tail helpers ----------------
__global__ void __launch_bounds__(256, 2) gemm2_f16(
    const float* __restrict__ A, const __half* __restrict__ Yt,
    float* __restrict__ P1, float* __restrict__ P2,
    float* __restrict__ RS1, float* __restrict__ RS2)
{
    extern __shared__ char smem[];
    const uint32_t sbase = smem_u32(smem);

    const int tid  = threadIdx.x;
    const int lane = tid & 31;
    const int wid  = tid >> 5;
    const int gid  = lane >> 2;
    const int tig  = lane & 3;
    const int wm   = wid >> 1;
    const int wn   = wid & 1;
    const int lrow = lane & 15;
    const int lhi  = (lane >> 4) & 1;

    const int ra = tid >> 3;
    const int sa = tid & 7;
    const int rb = tid >> 2;
    const int sb = tid & 3;

    const int bid = blockIdx.x;
    int segTile[6], segKs[6], segKe[6];
    int nseg;
    float* pout;
    float* rsout;
    if (bid < 256) {
        nseg = 1;
        segTile[0] = bid;
        segKs[0] = 0;
        segKe[0] = (bid >= LT0 && bid < LT1) ? 256 : KH;
        pout = P1; rsout = RS1;
    } else {
        const int j = bid - 256;                  // 0..39
        const int h0 = (j * 27) / 5;
        const int h1 = ((j + 1) * 27) / 5;
        nseg = h1 - h0;
        #pragma unroll
        for (int i = 0; i < 6; i++) {
            int h = h0 + i;
            segTile[i] = (h < LT0) ? h : h + 40;  // skip light tiles
            segKs[i] = KH;
            segKe[i] = 256;
        }
        pout = P2; rsout = RS2;
    }

    #pragma unroll 1
    for (int seg = 0; seg < nseg; seg++) {
        const int tile = segTile[seg];
        const int ks = segKs[seg];
        const int ke = segKe[seg];
        const int m0 = (tile >> 2) * T2_M;
        const int n0 = (tile & 3) * T2_N;
        const float*  gA = A  + (size_t)(m0 + ra) * N_ROWS + sa * 4;
        const __half* gB = Yt + (size_t)(n0 + rb) * N_ROWS + sb * 8;

        float acc[2][4][4];
        #pragma unroll
        for (int mi = 0; mi < 2; mi++)
            #pragma unroll
            for (int ni = 0; ni < 4; ni++)
                #pragma unroll
                for (int i = 0; i < 4; i++) acc[mi][ni][i] = 0.f;
        float rsum[4] = {0.f, 0.f, 0.f, 0.f};

        __syncthreads();   // prior-segment smem reads complete before reuse

        auto issueB = [&](int kc, int s6) {
            if (kc < ke)
                cpa16(sbase + B_OFF + s6 * B_ST + rb * (PAH * 2) + sb * 16,
                      gB + (size_t)kc * CK);
            asm volatile("cp.async.commit_group;" ::: "memory");
        };
        auto ldA = [&](int kc, float4* v) {
            #pragma unroll
            for (int i = 0; i < 4; i++)
                v[i] = *(const float4*)(gA + (size_t)i * 32 * N_ROWS + (size_t)kc * CK);
        };

        float4 vA[4];
        ldA(ks, vA);
        issueB(ks + 0, 0);
        issueB(ks + 1, 1);
        issueB(ks + 2, 2);
        issueB(ks + 3, 3);

        int s6c = 0, s6p = 4, p2 = 0;
        for (int kc = ks; kc < ke; kc++) {
            asm volatile("cp.async.wait_group %0;" :: "n"(3) : "memory");

            const uint32_t aw = sbase + p2 * A_ST + ra * (PAH * 2) + sa * 8;
            #pragma unroll
            for (int i = 0; i < 4; i++) {
                uint32_t h01 = pack_h2(vA[i].x, vA[i].y);
                uint32_t h23 = pack_h2(vA[i].z, vA[i].w);
                asm volatile("st.shared.v2.b32 [%0], {%1,%2};"
                             :: "r"(aw + i * 32 * (PAH * 2)), "r"(h01), "r"(h23));
                rsum[i] += (vA[i].x + vA[i].y) + (vA[i].z + vA[i].w);
            }
            const int kn = (kc + 1 < ke) ? kc + 1 : kc;
            ldA(kn, vA);

            __syncthreads();

            issueB(kc + 4, s6p);

            const uint32_t aBase = sbase + p2 * A_ST;
            const uint32_t bBase = sbase + B_OFF + s6c * B_ST;
            #pragma unroll
            for (int kh = 0; kh < 2; kh++) {
                uint32_t af[2][4], bf[4][2];
                #pragma unroll
                for (int mi = 0; mi < 2; mi++) {
                    uint32_t ad = aBase + ((wm * 32 + mi * 16 + lrow) * PAH + kh * 16 + lhi * 8) * 2;
                    ldsm4(af[mi][0], af[mi][1], af[mi][2], af[mi][3], ad);
                }
                #pragma unroll
                for (int np = 0; np < 2; np++) {
                    uint32_t bd = bBase + ((wn * 32 + np * 16 + lrow) * PAH + kh * 16 + lhi * 8) * 2;
                    uint32_t r0, r1, r2, r3;
                    ldsm4(r0, r1, r2, r3, bd);
                    bf[np * 2 + 0][0] = r0; bf[np * 2 + 0][1] = r2;
                    bf[np * 2 + 1][0] = r1; bf[np * 2 + 1][1] = r3;
                }
                #pragma unroll
                for (int mi = 0; mi < 2; mi++)
                    #pragma unroll
                    for (int ni = 0; ni < 4; ni++)
                        mma_f16_k16(acc[mi][ni], af[mi], bf[ni]);
            }

            s6c = (s6c == 5) ? 0 : s6c + 1;
            s6p = (s6p == 5) ? 0 : s6p + 1;
            p2 ^= 1;
        }

        // segment epilogue: rowsum (ntile==0 only) + raw partial tile
        #pragma unroll
        for (int i = 0; i < 4; i++) {
            rsum[i] += __shfl_down_sync(0xffffffffu, rsum[i], 4, 8);
            rsum[i] += __shfl_down_sync(0xffffffffu, rsum[i], 2, 8);
            rsum[i] += __shfl_down_sync(0xffffffffu, rsum[i], 1, 8);
        }
        if ((tile & 3) == 0 && sa == 0) {
            #pragma unroll
            for (int i = 0; i < 4; i++)
                rsout[m0 + i * 32 + ra] = rsum[i];
        }

        #pragma unroll
        for (int mi = 0; mi < 2; mi++) {
            const int r0 = m0 + wm * 32 + mi * 16 + gid;
            #pragma unroll
            for (int ni = 0; ni < 4; ni++) {
                const int cg = n0 + wn * 32 + ni * 8 + tig * 2;
                float2 v0, v1;
                v0.x = acc[mi][ni][0]; v0.y = acc[mi][ni][1];
                v1.x = acc[mi][ni][2]; v1.y = acc[mi][ni][3];
                *(float2*)(pout + (size_t)r0 * F_OUT + cg) = v0;
                *(float2*)(pout + (size_t)(r0 + 8) * F_OUT + cg) = v1;
            }
        }
    }
}

// ---------------- reduce: out = (P1 [+P2]) / (RS1 [+RS2]) + bias ----------------
__global__ void __launch_bounds__(256, 4) reduce_out(
    const float* __restrict__ P1, const float* __restrict__ P2,
    const float* __restrict__ RS1, const float* __restrict__ RS2,
    const float* __restrict__ bias, float* __restrict__ out)
{
    const int idx = blockIdx.x * 256 + threadIdx.x;   // over float4: 8192*64
    const int row = idx >> 6;
    const int col = (idx & 63) << 2;
    const int mt  = row >> 7;
    const bool light = (mt >= (LT0 >> 2)) && (mt < (LT1 >> 2));   // mtiles 27..36

    float rs = RS1[row];
    float4 s = reinterpret_cast<const float4*>(P1)[idx];
    if (!light) {
        rs += RS2[row];
        const float4 p = reinterpret_cast<const float4*>(P2)[idx];
        s.x += p.x; s.y += p.y; s.z += p.z; s.w += p.w;
    }
    const float inv = 1.f / fmaxf(rs, 1e-12f);
    const float4 bv = *(const float4*)(bias + col);
    float4 o;
    o.x = s.x * inv + bv.x;
    o.y = s.y * inv + bv.y;
    o.z = s.z * inv + bv.z;
    o.w = s.w * inv + bv.w;
    reinterpret_cast<float4*>(out)[idx] = o;
}

// ---------------- host ----------------
extern "C" void kernel_launch(void* const* d_in, const int* in_sizes, int n_in,
                              void* d_out, int out_size) {
    const float *A = nullptr, *X = nullptr, *W = nullptr, *Bi = nullptr;
    for (int i = 0; i < n_in; i++) {
        long s = in_sizes[i];
        if (s == (long)N_ROWS * N_ROWS)      A  = (const float*)d_in[i];
        else if (s == (long)N_ROWS * F_IN)   X  = (const float*)d_in[i];
        else if (s == (long)F_IN * F_OUT)    W  = (const float*)d_in[i];
        else if (s == (long)F_OUT)           Bi = (const float*)d_in[i];
    }

    void *xh = nullptr, *wth = nullptr, *yt = nullptr;
    void *p1 = nullptr, *p2 = nullptr, *rs1 = nullptr, *rs2 = nullptr;
    cudaGetSymbolAddress(&xh, g_Xh);
    cudaGetSymbolAddress(&wth, g_Wth);
    cudaGetSymbolAddress(&yt, g_Yt);
    cudaGetSymbolAddress(&p1, g_P1);
    cudaGetSymbolAddress(&p2, g_P2);
    cudaGetSymbolAddress(&rs1, g_RS1);
    cudaGetSymbolAddress(&rs2, g_RS2);

    cudaFuncSetAttribute(gemm1_f16, cudaFuncAttributeMaxDynamicSharedMemorySize, G1_SMEM);
    cudaFuncSetAttribute(gemm2_f16, cudaFuncAttributeMaxDynamicSharedMemorySize, T2_SMEM);

    prep_xh<<<(N_ROWS * F_IN / 4) / 256, 256>>>(X, (__half*)xh);
    prep_wt<<<dim3(F_OUT / 32, F_IN / 32), 256>>>(W, (__half*)wth);

    gemm1_f16<<<2 * 64, 256, G1_SMEM>>>((const __half*)wth, (const __half*)xh, (__half*)yt);

    gemm2_f16<<<296, 256, T2_SMEM>>>(A, (const __half*)yt,
                                     (float*)p1, (float*)p2, (float*)rs1, (float*)rs2);

    reduce_out<<<(N_ROWS * F_OUT / 4) / 256, 256>>>(
        (const float*)p1, (const float*)p2, (const float*)rs1, (const float*)rs2,
        Bi, (float*)d_out);
}

// round 10
// speedup vs baseline: 1.4023x; 1.2626x over previous
#include <cuda_runtime.h>
#include <cuda_fp16.h>
#include <cstdint>
#include <cstddef>

// ============================================================
// out = L1rownorm(A[8192,8192]) @ X[8192,512] @ W[512,256] + bias
//   Xh = fp16(X), Wth = fp16(W^T)
//   Yt[256,8192](fp16) = Wth @ Xh^T          (fp16 HMMA, tile 64x128, 256 CTAs)
//   out[m,:] = (A[m,:] @ Y)/sum(A[m,:]) + bias  (R6 gemm2: tile 128x64, 256 CTAs)
// ============================================================

#define N_ROWS 8192
#define F_IN   512
#define F_OUT  256

// ---- GEMM1 (fp16): tile 64x128 ----
#define PAH 40                       // halves per smem row (80 B)
#define A_ST1 (64 * PAH * 2)         // 5120
#define B_ST1 (128 * PAH * 2)        // 10240
#define STAGE1 (A_ST1 + B_ST1)       // 15360
#define G1_SMEM (3 * STAGE1)         // 46080

// ---- GEMM2 (fp16): tile 128x64 (R6 config) ----
#define T2_M 128
#define T2_N 64
#define CK 32
#define A_ST  (T2_M * PAH * 2)       // 10240
#define B_ST  (T2_N * PAH * 2)       // 5120
#define B_OFF (4 * A_ST)             // 4 A stages
#define RS_OFF (B_OFF + 8 * B_ST)    // 8 B stages -> 81920
#define T2_SMEM (RS_OFF + 128 * 4)   // 82432 -> 2 CTAs/SM

__device__ __align__(1024) __half g_Xh[(size_t)N_ROWS * F_IN];
__device__ __align__(1024) __half g_Wth[(size_t)F_OUT * F_IN];
__device__ __align__(1024) __half g_Yt[(size_t)F_OUT * N_ROWS];

// ---------------- device helpers ----------------
__device__ __forceinline__ uint32_t pack_h2(float lo, float hi) {
    uint32_t u;
    asm("cvt.rn.f16x2.f32 %0, %1, %2;" : "=r"(u) : "f"(hi), "f"(lo));
    return u;
}
__device__ __forceinline__ void mma_f16_k16(float* c, const uint32_t* a, const uint32_t* b) {
    asm volatile(
        "mma.sync.aligned.m16n8k16.row.col.f32.f16.f16.f32 "
        "{%0,%1,%2,%3}, {%4,%5,%6,%7}, {%8,%9}, {%0,%1,%2,%3};"
        : "+f"(c[0]), "+f"(c[1]), "+f"(c[2]), "+f"(c[3])
        : "r"(a[0]), "r"(a[1]), "r"(a[2]), "r"(a[3]), "r"(b[0]), "r"(b[1]));
}
__device__ __forceinline__ void cpa16(uint32_t s, const void* g) {
    asm volatile("cp.async.cg.shared.global [%0], [%1], 16;" :: "r"(s), "l"(g));
}
__device__ __forceinline__ void ldsm4(uint32_t& r0, uint32_t& r1, uint32_t& r2, uint32_t& r3,
                                      uint32_t addr) {
    asm volatile("ldmatrix.sync.aligned.m8n8.x4.shared.b16 {%0,%1,%2,%3}, [%4];"
                 : "=r"(r0), "=r"(r1), "=r"(r2), "=r"(r3) : "r"(addr));
}
__device__ __forceinline__ uint32_t smem_u32(const void* p) {
    uint32_t a;
    asm("{ .reg .u64 t; cvta.to.shared.u64 t, %1; cvt.u32.u64 %0, t; }" : "=r"(a) : "l"(p));
    return a;
}

// ---------------- prep kernels ----------------
__global__ void __launch_bounds__(256, 1) prep_xh(const float* __restrict__ x,
                                                  __half* __restrict__ xh) {
    int i = blockIdx.x * 256 + threadIdx.x;
    float4 v = reinterpret_cast<const float4*>(x)[i];
    uint2 o;
    o.x = pack_h2(v.x, v.y);
    o.y = pack_h2(v.z, v.w);
    reinterpret_cast<uint2*>(xh)[i] = o;
}
// coalesced transpose W[512,256] -> Wth[256,512] (fp16)
__global__ void __launch_bounds__(256, 1) prep_wt(const float* __restrict__ w,
                                                  __half* __restrict__ wth) {
    __shared__ float t[32][33];
    const int tx = threadIdx.x & 31;
    const int ty = threadIdx.x >> 5;          // 0..7
    const int fo0 = blockIdx.x * 32;          // 8 blocks
    const int fi0 = blockIdx.y * 32;          // 16 blocks
    #pragma unroll
    for (int r = 0; r < 32; r += 8)
        t[ty + r][tx] = w[(size_t)(fi0 + ty + r) * F_OUT + fo0 + tx];
    __syncthreads();
    #pragma unroll
    for (int r = 0; r < 32; r += 8)
        wth[(size_t)(fo0 + ty + r) * F_IN + fi0 + tx] = __float2half_rn(t[tx][ty + r]);
}

// ---------------- GEMM1 (fp16): Yt[256,8192] = Wth @ Xh^T, tile 64x128 ----------------
__global__ void __launch_bounds__(256, 2) gemm1_f16(
    const __half* __restrict__ P, const __half* __restrict__ Q,
    __half* __restrict__ out)
{
    extern __shared__ char smem[];
    const uint32_t sbase = smem_u32(smem);

    const int tid  = threadIdx.x;
    const int lane = tid & 31;
    const int wid  = tid >> 5;
    const int gid  = lane >> 2;
    const int tig  = lane & 3;
    const int wm   = wid >> 2;            // 0..1 (M strips of 32)
    const int wn   = wid & 3;             // 0..3 (N strips of 32)
    const int lrow = lane & 15;
    const int lhi  = (lane >> 4) & 1;

    const int mtile = blockIdx.x >> 6;    // 0..3
    const int ntile = blockIdx.x & 63;    // 0..63
    const int m0 = mtile * 64;
    const int n0 = ntile * 128;
    const int kchunks = F_IN / CK;        // 16

    const int rw = tid >> 2;              // 0..63
    const int sg = tid & 3;               // 0..3
    const __half* gA = P + (size_t)(m0 + rw) * F_IN + sg * 8;
    const __half* gB = Q + (size_t)(n0 + rw) * F_IN + sg * 8;

    auto issue = [&](int kc, int s) {
        uint32_t sA = sbase + s * STAGE1 + rw * 80 + sg * 16;
        uint32_t sB = sA + A_ST1;
        cpa16(sA,           gA + kc * CK);
        cpa16(sB,           gB + kc * CK);
        cpa16(sB + 64 * 80, gB + kc * CK + (size_t)64 * F_IN);
        asm volatile("cp.async.commit_group;" ::: "memory");
    };

    float acc[2][4][4];
    #pragma unroll
    for (int mi = 0; mi < 2; mi++)
        #pragma unroll
        for (int ni = 0; ni < 4; ni++)
            #pragma unroll
            for (int i = 0; i < 4; i++) acc[mi][ni][i] = 0.f;

    issue(0, 0);
    issue(1, 1);

    int s_c = 0, s_p = 2;
    for (int kc = 0; kc < kchunks; kc++) {
        asm volatile("cp.async.wait_group %0;" :: "n"(1) : "memory");
        __syncthreads();
        const uint32_t aBase = sbase + s_c * STAGE1;
        const uint32_t bBase = aBase + A_ST1;

        #pragma unroll
        for (int kh = 0; kh < 2; kh++) {
            uint32_t af[2][4], bf[4][2];
            #pragma unroll
            for (int mi = 0; mi < 2; mi++) {
                uint32_t ad = aBase + ((wm * 32 + mi * 16 + lrow) * PAH + kh * 16 + lhi * 8) * 2;
                ldsm4(af[mi][0], af[mi][1], af[mi][2], af[mi][3], ad);
            }
            #pragma unroll
            for (int np = 0; np < 2; np++) {
                uint32_t bd = bBase + ((wn * 32 + np * 16 + lrow) * PAH + kh * 16 + lhi * 8) * 2;
                uint32_t r0, r1, r2, r3;
                ldsm4(r0, r1, r2, r3, bd);
                bf[np * 2 + 0][0] = r0; bf[np * 2 + 0][1] = r2;
                bf[np * 2 + 1][0] = r1; bf[np * 2 + 1][1] = r3;
            }
            #pragma unroll
            for (int mi = 0; mi < 2; mi++)
                #pragma unroll
                for (int ni = 0; ni < 4; ni++)
                    mma_f16_k16(acc[mi][ni], af[mi], bf[ni]);
        }

        if (kc + 2 < kchunks) issue(kc + 2, s_p);
        else asm volatile("cp.async.commit_group;" ::: "memory");
        if (++s_c == 3) s_c = 0;
        if (++s_p == 3) s_p = 0;
    }

    #pragma unroll
    for (int mi = 0; mi < 2; mi++) {
        const int r0 = m0 + wm * 32 + mi * 16 + gid;
        #pragma unroll
        for (int ni = 0; ni < 4; ni++) {
            const int cg = n0 + wn * 32 + ni * 8 + tig * 2;
            *(uint32_t*)(out + (size_t)r0 * N_ROWS + cg) =
                pack_h2(acc[mi][ni][0], acc[mi][ni][1]);
            *(uint32_t*)(out + (size_t)(r0 + 8) * N_ROWS + cg) =
                pack_h2(acc[mi][ni][2], acc[mi][ni][3]);
        }
    }
}

// ---------------- GEMM2 (R6 config): out = (A @ Yt^T)*inv_rowsum + bias ----------------
__global__ void __launch_bounds__(256, 2) gemm2_f16(
    const float* __restrict__ A, const __half* __restrict__ Yt,
    float* __restrict__ out, const float* __restrict__ bias)
{
    extern __shared__ char smem[];
    const uint32_t sbase = smem_u32(smem);

    const int tid  = threadIdx.x;
    const int lane = tid & 31;
    const int wid  = tid >> 5;
    const int gid  = lane >> 2;
    const int tig  = lane & 3;
    const int wm   = wid >> 1;            // 0..3 (M strips of 32)
    const int wn   = wid & 1;             // 0..1 (N strips of 32)
    const int lrow = lane & 15;
    const int lhi  = (lane >> 4) & 1;

    const int mtile = blockIdx.x >> 2;    // 64
    const int ntile = blockIdx.x & 3;     // 4
    const int m0 = mtile * T2_M;
    const int n0 = ntile * T2_N;
    const int kchunks = N_ROWS / CK;      // 256

    const int ra = tid >> 3;              // 0..31  (A row mod 32)
    const int sa = tid & 7;               // 0..7   (A 16B segment)
    const int rb = tid >> 2;              // 0..63  (B row)
    const int sb = tid & 3;               // 0..3   (B 16B segment)
    const float*  gA = A  + (size_t)(m0 + ra) * N_ROWS + sa * 4;
    const __half* gB = Yt + (size_t)(n0 + rb) * N_ROWS + sb * 8;

    float acc[2][4][4];
    #pragma unroll
    for (int mi = 0; mi < 2; mi++)
        #pragma unroll
        for (int ni = 0; ni < 4; ni++)
            #pragma unroll
            for (int i = 0; i < 4; i++) acc[mi][ni][i] = 0.f;
    float rsum[4] = {0.f, 0.f, 0.f, 0.f};

    auto issueB = [&](int kc) {
        if (kc < kchunks) {
            cpa16(sbase + B_OFF + (kc & 7) * B_ST + rb * (PAH * 2) + sb * 16,
                  gB + (size_t)kc * CK);
            cpa16(sbase + B_OFF + ((kc + 1) & 7) * B_ST + rb * (PAH * 2) + sb * 16,
                  gB + (size_t)(kc + 1) * CK);
        }
        asm volatile("cp.async.commit_group;" ::: "memory");
    };
    auto ldA = [&](int kc, float4* v) {
        #pragma unroll
        for (int i = 0; i < 4; i++)
            v[i] = *(const float4*)(gA + (size_t)i * 32 * N_ROWS + (size_t)kc * CK);
    };
    auto stA = [&](int kc, const float4* v) {
        const uint32_t aw = sbase + (kc & 3) * A_ST + ra * (PAH * 2) + sa * 8;
        #pragma unroll
        for (int i = 0; i < 4; i++) {
            uint32_t h01 = pack_h2(v[i].x, v[i].y);
            uint32_t h23 = pack_h2(v[i].z, v[i].w);
            asm volatile("st.shared.v2.b32 [%0], {%1,%2};"
                         :: "r"(aw + i * 32 * (PAH * 2)), "r"(h01), "r"(h23));
            rsum[i] += (v[i].x + v[i].y) + (v[i].z + v[i].w);
        }
    };
    auto mmaChunk = [&](int kc) {
        const uint32_t aBase = sbase + (kc & 3) * A_ST;
        const uint32_t bBase = sbase + B_OFF + (kc & 7) * B_ST;
        #pragma unroll
        for (int ks = 0; ks < 2; ks++) {
            uint32_t af[2][4], bf[4][2];
            #pragma unroll
            for (int mi = 0; mi < 2; mi++) {
                uint32_t ad = aBase + ((wm * 32 + mi * 16 + lrow) * PAH + ks * 16 + lhi * 8) * 2;
                ldsm4(af[mi][0], af[mi][1], af[mi][2], af[mi][3], ad);
            }
            #pragma unroll
            for (int np = 0; np < 2; np++) {
                uint32_t bd = bBase + ((wn * 32 + np * 16 + lrow) * PAH + ks * 16 + lhi * 8) * 2;
                uint32_t r0, r1, r2, r3;
                ldsm4(r0, r1, r2, r3, bd);
                bf[np * 2 + 0][0] = r0; bf[np * 2 + 0][1] = r2;
                bf[np * 2 + 1][0] = r1; bf[np * 2 + 1][1] = r3;
            }
            #pragma unroll
            for (int mi = 0; mi < 2; mi++)
                #pragma unroll
                for (int ni = 0; ni < 4; ni++)
                    mma_f16_k16(acc[mi][ni], af[mi], bf[ni]);
        }
    };

    // prologue
    float4 vA0[4], vA1[4];
    ldA(0, vA0);
    ldA(1, vA1);
    issueB(0);
    issueB(2);

    for (int kc = 0; kc < kchunks; kc += 2) {
        asm volatile("cp.async.wait_group %0;" :: "n"(1) : "memory");

        stA(kc, vA0);
        stA(kc + 1, vA1);
        int kn0 = kc + 2, kn1 = kc + 3;
        if (kn1 >= kchunks) { kn0 = kchunks - 2; kn1 = kchunks - 1; }
        ldA(kn0, vA0);
        ldA(kn1, vA1);

        __syncthreads();

        issueB(kc + 4);

        mmaChunk(kc);
        mmaChunk(kc + 1);
    }

    // rowsum reduce (8 lanes per row group)
    #pragma unroll
    for (int i = 0; i < 4; i++) {
        rsum[i] += __shfl_down_sync(0xffffffffu, rsum[i], 4, 8);
        rsum[i] += __shfl_down_sync(0xffffffffu, rsum[i], 2, 8);
        rsum[i] += __shfl_down_sync(0xffffffffu, rsum[i], 1, 8);
    }
    float* rs = (float*)(smem + RS_OFF);
    if (sa == 0) {
        #pragma unroll
        for (int i = 0; i < 4; i++)
            rs[i * 32 + ra] = 1.f / fmaxf(rsum[i], 1e-12f);
    }
    __syncthreads();

    // epilogue
    #pragma unroll
    for (int mi = 0; mi < 2; mi++) {
        const int r0 = wm * 32 + mi * 16 + gid;
        const float i0 = rs[r0];
        const float i1 = rs[r0 + 8];
        #pragma unroll
        for (int ni = 0; ni < 4; ni++) {
            const int cg = n0 + wn * 32 + ni * 8 + tig * 2;
            float2 bv = *(const float2*)(bias + cg);
            float2 v0, v1;
            v0.x = acc[mi][ni][0] * i0 + bv.x;
            v0.y = acc[mi][ni][1] * i0 + bv.y;
            v1.x = acc[mi][ni][2] * i1 + bv.x;
            v1.y = acc[mi][ni][3] * i1 + bv.y;
            *(float2*)(out + (size_t)(m0 + r0) * F_OUT + cg) = v0;
            *(float2*)(out + (size_t)(m0 + r0 + 8) * F_OUT + cg) = v1;
        }
    }
}

// ---------------- host ----------------
extern "C" void kernel_launch(void* const* d_in, const int* in_sizes, int n_in,
                              void* d_out, int out_size) {
    const float *A = nullptr, *X = nullptr, *W = nullptr, *Bi = nullptr;
    for (int i = 0; i < n_in; i++) {
        long s = in_sizes[i];
        if (s == (long)N_ROWS * N_ROWS)      A  = (const float*)d_in[i];
        else if (s == (long)N_ROWS * F_IN)   X  = (const float*)d_in[i];
        else if (s == (long)F_IN * F_OUT)    W  = (const float*)d_in[i];
        else if (s == (long)F_OUT)           Bi = (const float*)d_in[i];
    }

    void *xh = nullptr, *wth = nullptr, *yt = nullptr;
    cudaGetSymbolAddress(&xh, g_Xh);
    cudaGetSymbolAddress(&wth, g_Wth);
    cudaGetSymbolAddress(&yt, g_Yt);

    cudaFuncSetAttribute(gemm1_f16, cudaFuncAttributeMaxDynamicSharedMemorySize, G1_SMEM);
    cudaFuncSetAttribute(gemm2_f16, cudaFuncAttributeMaxDynamicSharedMemorySize, T2_SMEM);

    prep_xh<<<(N_ROWS * F_IN / 4) / 256, 256>>>(X, (__half*)xh);
    prep_wt<<<dim3(F_OUT / 32, F_IN / 32), 256>>>(W, (__half*)wth);

    // GEMM1: Yt[256,8192] = Wth @ Xh^T   (4 x 64 = 256 CTAs, tile 64x128)
    gemm1_f16<<<4 * 64, 256, G1_SMEM>>>((const __half*)wth, (const __half*)xh, (__half*)yt);

    // GEMM2: out[8192,256] = (A @ Yt^T)*inv_rowsum + bias  (64 x 4 = 256 CTAs)
    gemm2_f16<<<64 * 4, 256, T2_SMEM>>>(A, (const __half*)yt, (float*)d_out, Bi);
}